// round 9
// baseline (speedup 1.0000x reference)
#include <cuda_runtime.h>
#include <cuda_bf16.h>
#include <cstdint>

// InverseAvgPool1d, K=8 -> half=4, s=9.
// S'[t] = 8*A[t] - 8*x0*[t%9 <= 4],  A[t] = stride-9 prefix sum of x.
// out[t] = S'[t] - S'[t-1]   (S'[-1] = 0).  Correction folded into writeback.
//
// One row per CTA, 9 warps = 9 residue chains. Row staged into smem with a
// single one-shot TMA bulk copy (no per-thread LDG/STS); threads wait on the
// mbarrier. Gather/writeback slots are lane-private => no barrier between.

#define ROW_T 4096
#define ROW_BYTES 16384
#define NWARP 9
#define NTHREADS (NWARP * 32)   // 288
#define PER_LANE 15             // 32*15 = 480 slots; real max 456

__global__ __launch_bounds__(NTHREADS)
void inv_avgpool_kernel(const float* __restrict__ x, float* __restrict__ out) {
    __shared__ __align__(16) float s[ROW_T];
    __shared__ __align__(8) unsigned long long mbar;

    const int tid = threadIdx.x;
    const int lane = tid & 31;
    const int r = tid >> 5;                  // residue chain 0..8

    const size_t row = blockIdx.x;
    float4* __restrict__ outr = (float4*)(out + row * ROW_T);

    const uint32_t mb = (uint32_t)__cvta_generic_to_shared(&mbar);
    const uint32_t sb = (uint32_t)__cvta_generic_to_shared(&s[0]);

    if (tid == 0) {
        asm volatile("mbarrier.init.shared.b64 [%0], 1;" :: "r"(mb) : "memory");
        asm volatile("fence.proxy.async.shared::cta;" ::: "memory");
    }
    __syncthreads();
    if (tid == 0) {
        asm volatile("mbarrier.arrive.expect_tx.shared.b64 _, [%0], %1;"
                     :: "r"(mb), "r"(ROW_BYTES) : "memory");
        asm volatile("cp.async.bulk.shared::cta.global.mbarrier::complete_tx::bytes "
                     "[%0], [%1], %2, [%3];"
                     :: "r"(sb), "l"(x + row * ROW_T), "r"(ROW_BYTES), "r"(mb)
                     : "memory");
    }

    // x0 via global broadcast (independent of the TMA wait)
    const float x0 = __ldg(x + row * ROW_T);

    // wait for the row (acquire orders the TMA data for all threads)
    asm volatile(
        "{\n\t.reg .pred P;\n\t"
        "LAB_W%=:\n\t"
        "mbarrier.try_wait.parity.acquire.cta.shared::cta.b64 P, [%0], 0, 0x989680;\n\t"
        "@P bra.uni LAB_D%=;\n\t"
        "bra.uni LAB_W%=;\n\t"
        "LAB_D%=:\n\t}"
        :: "r"(mb) : "memory");

    const int base = r + 135 * lane;         // lanes 0..29: base+126 <= 4049
    const int lim30 = (r == 0) ? 6 : 5;      // lane 30 valid count

    // gather: lane l accumulates chain slots [15l, 15l+15) (lane-private)
    float a[PER_LANE];
    float run = 0.f;
    if (lane < 30) {
        #pragma unroll
        for (int j = 0; j < PER_LANE; j++) { run += s[base + 9 * j]; a[j] = run; }
    } else if (lane == 30) {
        #pragma unroll
        for (int j = 0; j < PER_LANE; j++) {
            if (j < lim30) run += s[base + 9 * j];
            a[j] = run;
        }
    }

    // warp scan over lane totals -> exclusive carry
    float incl = run;
    #pragma unroll
    for (int off = 1; off < 32; off <<= 1) {
        float up = __shfl_up_sync(0xffffffffu, incl, off);
        if (lane >= off) incl += up;
    }
    float e8 = 8.f * (incl - run);
    if (r <= 4) e8 -= 8.f * x0;              // fold x0 correction into S'

    // writeback S' in place — same lane-private slots, no barrier needed
    if (lane < 30) {
        #pragma unroll
        for (int j = 0; j < PER_LANE; j++) s[base + 9 * j] = fmaf(8.f, a[j], e8);
    } else if (lane == 30) {
        #pragma unroll
        for (int j = 0; j < PER_LANE; j++)
            if (j < lim30) s[base + 9 * j] = fmaf(8.f, a[j], e8);
    }
    __syncthreads();

    // diff pass: out[t] = S'[t] - S'[t-1], streaming stores
    #pragma unroll
    for (int q = tid; q < ROW_T / 4; q += NTHREADS) {
        float4 B = ((const float4*)s)[q];
        float prevw = __shfl_up_sync(0xffffffffu, B.w, 1);
        if (lane == 0) prevw = (q == 0) ? 0.f : s[4 * q - 1];
        float4 o;
        o.x = B.x - prevw;
        o.y = B.y - B.x;
        o.z = B.z - B.y;
        o.w = B.w - B.z;
        __stcs(outr + q, o);
    }
}

extern "C" void kernel_launch(void* const* d_in, const int* in_sizes, int n_in,
                              void* d_out, int out_size) {
    const float* x = (const float*)d_in[0];
    float* out = (float*)d_out;
    const int rows = in_sizes[0] / ROW_T;   // 16384
    inv_avgpool_kernel<<<rows, NTHREADS>>>(x, out);
}